// round 2
// baseline (speedup 1.0000x reference)
#include <cuda_runtime.h>
#include <math.h>

#define N_NODES 100000
#define N_EDGES 1600000
#define F_IN    128
#define E_DIM   16
#define HID     64
#define G_NUM   64
#define OUT_DIM 10

// ---------------- scratch (device globals; no allocations allowed) ----------------
__device__ __align__(16) float g_xtrans[N_NODES * HID];   // 25.6 MB
__device__ __align__(16) float g_skip[N_NODES * HID];     // 25.6 MB
__device__ float  g_ax[N_NODES];
__device__ __align__(16) float g_acc[N_NODES * 128];      // [wx(64) | wh(64)] per node, 51.2 MB
__device__ float  g_den[N_NODES];
__device__ __align__(16) float g_wt[128 * 128];           // [k][c] c<64: W_lin col, c>=64: W_skip col
__device__ __align__(16) float2 g_we1t2[16 * 32];         // [k][lane] = (W_e1[2l][k], W_e1[2l+1][k])
__device__ __align__(16) float g_u[64];                   // u[h] = sum_d W_e2[d][h]*att[d]
__device__ float  g_hloop[64];                            // relu(b_e1)
__device__ float  g_cscal[1];                             // b_e2 . att
__device__ float  g_aloop[1];                             // hloop.u + c
__device__ float  g_sums[G_NUM * HID];
__device__ float  g_cnt[G_NUM];

// ---------------- f32x2 helpers (FFMA2: 2x fp32 throughput on Blackwell) ----------
__device__ __forceinline__ unsigned long long pack2(float x, float y) {
    unsigned long long r;
    asm("mov.b64 %0, {%1, %2};" : "=l"(r) : "f"(x), "f"(y));
    return r;
}
__device__ __forceinline__ void unpack2(unsigned long long v, float& x, float& y) {
    asm("mov.b64 {%0, %1}, %2;" : "=f"(x), "=f"(y) : "l"(v));
}
__device__ __forceinline__ unsigned long long fma2(unsigned long long a, unsigned long long b,
                                                   unsigned long long c) {
    unsigned long long d;
    asm("fma.rn.f32x2 %0, %1, %2, %3;" : "=l"(d) : "l"(a), "l"(b), "l"(c));
    return d;
}
__device__ __forceinline__ unsigned long long add2(unsigned long long a, unsigned long long b) {
    unsigned long long d;
    asm("add.rn.f32x2 %0, %1, %2;" : "=l"(d) : "l"(a), "l"(b));
    return d;
}

// ---------------- K_pre: weight transposes + attention-folded constants -----------
__global__ void kpre(const float* __restrict__ Wlin, const float* __restrict__ Wskip,
                     const float* __restrict__ We1,  const float* __restrict__ be1,
                     const float* __restrict__ We2,  const float* __restrict__ be2,
                     const float* __restrict__ att) {
    int t = threadIdx.x;  // 256 threads, 1 block
    for (int i = t; i < 128 * 128; i += 256) {
        int k = i >> 7, c = i & 127;
        g_wt[i] = (c < 64) ? Wlin[c * 128 + k] : Wskip[(c - 64) * 128 + k];
    }
    for (int i = t; i < 16 * 32; i += 256) {
        int k = i >> 5, l = i & 31;
        g_we1t2[i] = make_float2(We1[(2 * l) * 16 + k], We1[(2 * l + 1) * 16 + k]);
    }
    if (t < 64) {
        float uu = 0.f;
        for (int d = 0; d < 64; d++) uu += We2[d * 64 + t] * att[d];
        g_u[t] = uu;
        g_hloop[t] = fmaxf(be1[t], 0.f);
    }
    __syncthreads();
    if (t == 0) {
        float cc = 0.f;
        for (int d = 0; d < 64; d++) cc += be2[d] * att[d];
        g_cscal[0] = cc;
        float al = cc;
        for (int h = 0; h < 64; h++) al += g_hloop[h] * g_u[h];
        g_aloop[0] = al;
    }
}

// ---------------- K_node: [N,128] @ [128,128] -> x_trans | skip, plus a_x ---------
__global__ __launch_bounds__(256) void k_node(const float* __restrict__ x,
                                              const float* __restrict__ att) {
    __shared__ __align__(16) float xs[64 * 64];     // 64 nodes x 64 k chunk
    __shared__ __align__(16) float wsm[64 * 128];   // 64 k x 128 cols (k-major)
    int t = threadIdx.x, lane = t & 31, w = t >> 5;
    int nodeBase = blockIdx.x * 64;

    unsigned long long acc[8][2];
#pragma unroll
    for (int n = 0; n < 8; n++) { acc[n][0] = pack2(0.f, 0.f); acc[n][1] = pack2(0.f, 0.f); }

    for (int kb = 0; kb < 128; kb += 64) {
#pragma unroll
        for (int j = 0; j < 4; j++) {
            int i4 = t + j * 256;            // 0..1023 float4s
            int nl = i4 >> 4, kk4 = i4 & 15;
            int node = nodeBase + nl;
            float4 v = make_float4(0.f, 0.f, 0.f, 0.f);
            if (node < N_NODES) v = __ldg((const float4*)x + node * 32 + (kb >> 2) + kk4);
            ((float4*)xs)[nl * 16 + kk4] = v;
        }
#pragma unroll
        for (int j = 0; j < 8; j++) {
            int i4 = t + j * 256;            // 0..2047 float4s
            int kk = i4 >> 5, c4 = i4 & 31;
            ((float4*)wsm)[i4] = ((const float4*)g_wt)[(kb + kk) * 32 + c4];
        }
        __syncthreads();
#pragma unroll 8
        for (int k = 0; k < 64; k++) {
            ulonglong2 wv = ((const ulonglong2*)wsm)[k * 32 + lane];
#pragma unroll
            for (int n = 0; n < 8; n++) {
                float xv = xs[(w * 8 + n) * 64 + k];
                unsigned long long xb = pack2(xv, xv);
                acc[n][0] = fma2(xb, wv.x, acc[n][0]);
                acc[n][1] = fma2(xb, wv.y, acc[n][1]);
            }
        }
        __syncthreads();
    }

    float4 av = make_float4(0.f, 0.f, 0.f, 0.f);
    if (lane < 16) av = __ldg((const float4*)att + lane);
#pragma unroll
    for (int n = 0; n < 8; n++) {
        int node = nodeBase + w * 8 + n;
        float o0, o1, o2, o3;
        unpack2(acc[n][0], o0, o1);
        unpack2(acc[n][1], o2, o3);
        float part = o0 * av.x + o1 * av.y + o2 * av.z + o3 * av.w;  // lanes>=16 contribute 0
#pragma unroll
        for (int off = 16; off; off >>= 1) part += __shfl_xor_sync(0xffffffffu, part, off);
        if (node < N_NODES) {
            float4 v = make_float4(o0, o1, o2, o3);
            if (lane < 16) ((float4*)g_xtrans)[node * 16 + lane] = v;
            else           ((float4*)g_skip)[node * 16 + (lane - 16)] = v;
            if (lane == 0) g_ax[node] = part;
        }
    }
}

// ---------------- K_edge: one warp per edge, grid-stride --------------------------
__global__ __launch_bounds__(256) void k_edge(const int* __restrict__ ei,
                                              const float* __restrict__ ea,
                                              const float* __restrict__ be1) {
    int lane = threadIdx.x & 31;
    int warp = (blockIdx.x * blockDim.x + threadIdx.x) >> 5;
    int nwarps = (gridDim.x * blockDim.x) >> 5;

    // persistent per-warp weights: lane owns e_hidden dims (2l, 2l+1)
    unsigned long long w2[16];
#pragma unroll
    for (int k = 0; k < 16; k++) {
        float2 f = g_we1t2[k * 32 + lane];
        w2[k] = pack2(f.x, f.y);
    }
    float2 bias = __ldg((const float2*)be1 + lane);
    float2 uu = *((const float2*)g_u + lane);
    float cconst = g_cscal[0];

    for (int e = warp; e < N_EDGES; e += nwarps) {
        int src = __ldg(ei + e);
        int dst = __ldg(ei + N_EDGES + e);
        const float4* p = (const float4*)(ea + (size_t)e * 16);
        float4 A = __ldg(p), B = __ldg(p + 1), C = __ldg(p + 2), D = __ldg(p + 3);
        float ev[16] = {A.x, A.y, A.z, A.w, B.x, B.y, B.z, B.w,
                        C.x, C.y, C.z, C.w, D.x, D.y, D.z, D.w};
        unsigned long long h2a = pack2(bias.x, bias.y);
        unsigned long long h2b = pack2(0.f, 0.f);
#pragma unroll
        for (int k = 0; k < 16; k += 2) {
            h2a = fma2(pack2(ev[k], ev[k]), w2[k], h2a);
            h2b = fma2(pack2(ev[k + 1], ev[k + 1]), w2[k + 1], h2b);
        }
        float h0, h1;
        unpack2(add2(h2a, h2b), h0, h1);
        h0 = fmaxf(h0, 0.f); h1 = fmaxf(h1, 0.f);

        float pr = h0 * uu.x + h1 * uu.y;
#pragma unroll
        for (int off = 16; off; off >>= 1) pr += __shfl_xor_sync(0xffffffffu, pr, off);

        float alpha = __ldg(&g_ax[src]) + pr + cconst;
        alpha = alpha > 0.f ? alpha : 0.2f * alpha;   // leaky_relu(0.2)
        float wgt = __expf(alpha);                    // no max-sub: safe range, softmax-invariant

        float4 xv = make_float4(0.f, 0.f, 0.f, 0.f);
        if (lane < 16) xv = __ldg((const float4*)g_xtrans + src * 16 + lane);
        int j = lane & 15;
        float ga = __shfl_sync(0xffffffffu, h0, 2 * j);
        float gb = __shfl_sync(0xffffffffu, h1, 2 * j);
        float gc = __shfl_sync(0xffffffffu, h0, 2 * j + 1);
        float gd = __shfl_sync(0xffffffffu, h1, 2 * j + 1);
        float4 v;
        if (lane < 16) v = make_float4(wgt * xv.x, wgt * xv.y, wgt * xv.z, wgt * xv.w);
        else           v = make_float4(wgt * ga, wgt * gb, wgt * gc, wgt * gd);

        float* ptr = g_acc + dst * 128 + 4 * lane;    // warp covers full 512B row: coalesced
        asm volatile("red.global.add.v4.f32 [%0], {%1,%2,%3,%4};"
                     :: "l"(ptr), "f"(v.x), "f"(v.y), "f"(v.z), "f"(v.w) : "memory");
        if (lane == 0) atomicAdd(&g_den[dst], wgt);
    }
}

// ---------------- K_final: per-node GEMV + normalize + skip + pooled sums ---------
__global__ __launch_bounds__(256) void k_final(const float* __restrict__ We2,
                                               const float* __restrict__ be2,
                                               const int* __restrict__ batch,
                                               float* __restrict__ out) {
    __shared__ float Ws[64 * 65];   // padded: bank-conflict-free column reads
    __shared__ float hs[4][64];
    int t = threadIdx.x;
    for (int i = t; i < 4096; i += 256) Ws[(i >> 6) * 65 + (i & 63)] = __ldg(&We2[i]);

    int grp = t >> 6, d = t & 63;
    int i = blockIdx.x * 4 + grp;
    float aloop = g_aloop[0];
    float wi = 0.f, den = 0.f, accx = 0.f, xt = 0.f, sk = 0.f;
    if (i < N_NODES) {
        float al = g_ax[i] + aloop;
        al = al > 0.f ? al : 0.2f * al;
        wi = __expf(al);
        den = g_den[i] + wi;
        accx = g_acc[i * 128 + d];
        float acch = g_acc[i * 128 + 64 + d];
        hs[grp][d] = acch + wi * g_hloop[d];
        xt = g_xtrans[i * 64 + d];
        sk = g_skip[i * 64 + d];
    } else {
        hs[grp][d] = 0.f;
    }
    __syncthreads();
    if (i < N_NODES) {
        float s = 0.f;
#pragma unroll 8
        for (int h = 0; h < 64; h++) s += hs[grp][h] * Ws[d * 65 + h];
        float o = accx + wi * xt + s + den * __ldg(&be2[d]);
        float xo = o / (den + 1e-16f) + sk;
        out[i * 64 + d] = xo;
        int gb = __ldg(&batch[i]);
        atomicAdd(&g_sums[gb * 64 + d], xo);
        if (d == 0) atomicAdd(&g_cnt[gb], 1.0f);
    }
}

// ---------------- K_cls: pool-normalize + MLP head --------------------------------
__global__ void k_cls(const float* __restrict__ Wc1, const float* __restrict__ bc1,
                      const float* __restrict__ Wc2, const float* __restrict__ bc2,
                      float* __restrict__ out) {
    __shared__ float reps[4096];
    __shared__ float hid[4096];
    int t = threadIdx.x;  // 256
    for (int i = t; i < 4096; i += 256) {
        int g = i >> 6;
        float cnt = fmaxf(g_cnt[g], 1.f);
        float r = g_sums[i] / cnt;
        reps[i] = r;
        out[N_NODES * 64 + i] = r;
    }
    __syncthreads();
    for (int i = t; i < 4096; i += 256) {
        int g = i >> 6, d = i & 63;
        float s = __ldg(&bc1[d]);
        for (int h = 0; h < 64; h++) s += reps[g * 64 + h] * __ldg(&Wc1[d * 64 + h]);
        hid[i] = fmaxf(s, 0.f);
    }
    __syncthreads();
    for (int i = t; i < 640; i += 256) {
        int g = i / 10, o = i % 10;
        float s = __ldg(&bc2[o]);
        for (int h = 0; h < 64; h++) s += hid[g * 64 + h] * __ldg(&Wc2[o * 64 + h]);
        out[N_NODES * 64 + 4096 + i] = s;
    }
}

// ---------------- launch -----------------------------------------------------------
extern "C" void kernel_launch(void* const* d_in, const int* in_sizes, int n_in,
                              void* d_out, int out_size) {
    const float* x     = (const float*)d_in[0];
    const int*   ei    = (const int*)d_in[1];
    const float* ea    = (const float*)d_in[2];
    const int*   batch = (const int*)d_in[3];
    const float* Wlin  = (const float*)d_in[4];
    const float* We1   = (const float*)d_in[5];
    const float* be1   = (const float*)d_in[6];
    const float* We2   = (const float*)d_in[7];
    const float* be2   = (const float*)d_in[8];
    const float* att   = (const float*)d_in[9];
    const float* Wskip = (const float*)d_in[10];
    const float* Wc1   = (const float*)d_in[11];
    const float* bc1   = (const float*)d_in[12];
    const float* Wc2   = (const float*)d_in[13];
    const float* bc2   = (const float*)d_in[14];
    float* out = (float*)d_out;

    void *pacc, *pden, *psum, *pcnt;
    cudaGetSymbolAddress(&pacc, g_acc);
    cudaGetSymbolAddress(&pden, g_den);
    cudaGetSymbolAddress(&psum, g_sums);
    cudaGetSymbolAddress(&pcnt, g_cnt);
    cudaMemsetAsync(pacc, 0, sizeof(float) * (size_t)N_NODES * 128);
    cudaMemsetAsync(pden, 0, sizeof(float) * N_NODES);
    cudaMemsetAsync(psum, 0, sizeof(float) * G_NUM * HID);
    cudaMemsetAsync(pcnt, 0, sizeof(float) * G_NUM);

    kpre<<<1, 256>>>(Wlin, Wskip, We1, be1, We2, be2, att);
    k_node<<<(N_NODES + 63) / 64, 256>>>(x, att);
    k_edge<<<1184, 256>>>(ei, ea, be1);
    k_final<<<(N_NODES + 3) / 4, 256>>>(We2, be2, batch, out);
    k_cls<<<1, 256>>>(Wc1, bc1, Wc2, bc2, out);
}